// round 16
// baseline (speedup 1.0000x reference)
#include <cuda_runtime.h>

// ---------------- problem constants ----------------
#define TT 256
#define D1 512
#define HW1 (512*512)
#define HW2 (256*256)
#define HW4 (128*128)
#define HW8 (64*64)

// ---------------- device scratch (no allocations allowed) ----------------
__device__ float g_img2[(size_t)TT * HW2];
__device__ float g_img4[(size_t)TT * HW4];
__device__ float g_img8[(size_t)TT * HW8];
__device__ float g_s[4 * TT];

__device__ __forceinline__ void st_cs(float* p, float v) {
    asm volatile("st.global.cs.f32 [%0], %1;" :: "l"(p), "f"(v) : "memory");
}
__device__ __forceinline__ void st_cs2(float* p, float a, float b) {
    asm volatile("st.global.cs.v2.f32 [%0], {%1,%2};"
                 :: "l"(p), "f"(a), "f"(b) : "memory");
}
__device__ __forceinline__ void st_cs4(float* p, float4 v) {
    asm volatile("st.global.cs.v4.f32 [%0], {%1,%2,%3,%4};"
                 :: "l"(p), "f"(v.x), "f"(v.y), "f"(v.z), "f"(v.w) : "memory");
}

__global__ void zero_s_kernel() {
    g_s[threadIdx.x] = 0.0f;
}

// ============ verified R15 core: 4-high single column, precomputed coords ============
template<int DIM>
__device__ __forceinline__ void sample_column_at(
    const float* __restrict__ base, const float* __restrict__ Wk,
    float* __restrict__ xreg, size_t obase,
    int w, int h0,
    float ix0, float iy0, float th1, float th4,
    float& c)
{
    // ---- warp-uniform fast path ----
    {
        const float fx0f = floorf(ix0), fy0f = floorf(iy0);
        const int x0 = (int)fx0f, y0 = (int)fy0f;
        const float fx = ix0 - fx0f, fy = iy0 - fy0f;
        const float dy = th4 - 1.0f;
        const float wxe = fmaf(3.0f, th1, fx);
        const float wye = fmaf(3.0f, dy,  fy);
        const bool ok = (wxe >= 0.0f) & (wxe < 1.0f)
                      & (wye >= 0.0f) & (wye < 1.0f)
                      & (x0 >= 0) & (x0 < DIM - 1)
                      & (y0 >= 0) & (y0 <= DIM - 5);
        if (__all_sync(0xffffffffu, ok)) {
            float va[5], vb[5];
            const float* r = base + (size_t)y0 * DIM + x0;
#pragma unroll
            for (int k = 0; k < 5; k++) {
                va[k] = __ldg(r);
                vb[k] = __ldg(r + 1);
                r += DIM;
            }
            float wk[4];
#pragma unroll
            for (int j = 0; j < 4; j++)
                wk[j] = __ldg(Wk + (h0 + j) * DIM + w);
#pragma unroll
            for (int j = 0; j < 4; j++) {
                const float wx = fmaf((float)j, th1, fx);
                const float wy = fmaf((float)j, dy,  fy);
                const float top = fmaf(vb[j],     wx, va[j]     * (1.0f - wx));
                const float bot = fmaf(vb[j + 1], wx, va[j + 1] * (1.0f - wx));
                const float val = fmaf(bot, wy, top * (1.0f - wy));
                st_cs(xreg + obase + (size_t)j * DIM, val);
                c = fmaf(val, wk[j], c);
            }
            return;
        }
    }

    // ---- general path (verified): per-j gathers, interior/border split ----
    const float ix3 = fmaf(3.0f, th1, ix0);
    const float iy3 = fmaf(3.0f, th4, iy0);
    const bool interior =
        fminf(ix0, ix3) >= 0.0f && fmaxf(ix0, ix3) < (float)(DIM - 1) &&
        fminf(iy0, iy3) >= 0.0f && fmaxf(iy0, iy3) < (float)(DIM - 1);

    if (interior) {
        float v00[4], v01[4], v10[4], v11[4], wxs[4], wys[4], wk[4];
#pragma unroll
        for (int j = 0; j < 4; j++) {
            const float ix = fmaf((float)j, th1, ix0);
            const float iy = fmaf((float)j, th4, iy0);
            const float fx = floorf(ix), fy = floorf(iy);
            const int x0 = (int)fx, y0 = (int)fy;
            wxs[j] = ix - fx; wys[j] = iy - fy;
            const float* r0 = base + (size_t)y0 * DIM + x0;
            const float* r1 = r0 + DIM;
            v00[j] = __ldg(r0);
            v01[j] = __ldg(r0 + 1);
            v10[j] = __ldg(r1);
            v11[j] = __ldg(r1 + 1);
            wk[j]  = __ldg(Wk + (h0 + j) * DIM + w);
        }
#pragma unroll
        for (int j = 0; j < 4; j++) {
            const float wx = wxs[j], wy = wys[j];
            const float top = fmaf(v01[j], wx, v00[j] * (1.0f - wx));
            const float bot = fmaf(v11[j], wx, v10[j] * (1.0f - wx));
            const float val = fmaf(bot, wy, top * (1.0f - wy));
            st_cs(xreg + obase + (size_t)j * DIM, val);
            c = fmaf(val, wk[j], c);
        }
    } else {
#pragma unroll
        for (int j = 0; j < 4; j++) {
            const float ix = fmaf((float)j, th1, ix0);
            const float iy = fmaf((float)j, th4, iy0);
            const float fx = floorf(ix), fy = floorf(iy);
            const int x0 = (int)fx, y0 = (int)fy;
            const float wx = ix - fx, wy = iy - fy;

            const bool x0v = (unsigned)x0       < (unsigned)DIM;
            const bool x1v = (unsigned)(x0 + 1) < (unsigned)DIM;
            const bool y0v = (unsigned)y0       < (unsigned)DIM;
            const bool y1v = (unsigned)(y0 + 1) < (unsigned)DIM;

            const int x0c = min(max(x0, 0), DIM - 1);
            const int x1c = min(max(x0 + 1, 0), DIM - 1);
            const int y0c = min(max(y0, 0), DIM - 1);
            const int y1c = min(max(y0 + 1, 0), DIM - 1);

            const float* r0 = base + (size_t)y0c * DIM;
            const float* r1 = base + (size_t)y1c * DIM;
            const float a00 = __ldg(r0 + x0c);
            const float a01 = __ldg(r0 + x1c);
            const float a10 = __ldg(r1 + x0c);
            const float a11 = __ldg(r1 + x1c);

            const float wx1 = x1v ? wx : 0.0f;
            const float wx0 = x0v ? (1.0f - wx) : 0.0f;
            const float wy1 = y1v ? wy : 0.0f;
            const float wy0 = y0v ? (1.0f - wy) : 0.0f;

            const float top = fmaf(a01, wx1, a00 * wx0);
            const float bot = fmaf(a11, wx1, a10 * wx0);
            const float val = fmaf(bot, wy1, top * wy0);
            st_cs(xreg + obase + (size_t)j * DIM, val);
            c = fmaf(val, __ldg(Wk + (h0 + j) * DIM + w), c);
        }
    }
}

// ============ 2-wide x 4-high tile: shared-column fast path ============
// Pixels (w, h0..h0+3) and (w+1, h0..h0+3). w must be even.
template<int DIM>
__device__ __forceinline__ void sample_pair4(
    const float* __restrict__ base, const float* __restrict__ theta_t,
    const float* __restrict__ Wk, float* __restrict__ xreg,
    size_t obase, int w, int h0, float& c)
{
    const float th0 = __ldg(theta_t + 0), th1 = __ldg(theta_t + 1), th2 = __ldg(theta_t + 2);
    const float th3 = __ldg(theta_t + 3), th4 = __ldg(theta_t + 4), th5 = __ldg(theta_t + 5);

    constexpr float inv  = 2.0f / (float)DIM;
    constexpr float half = 0.5f * (float)DIM;
    const float xn  = ((float)w  + 0.5f) * inv - 1.0f;
    const float yn0 = ((float)h0 + 0.5f) * inv - 1.0f;
    const float gx0 = fmaf(th0, xn, fmaf(th1, yn0, th2));
    const float gy0 = fmaf(th3, xn, fmaf(th4, yn0, th5));
    const float ix0 = fmaf(gx0 + 1.0f, half, -0.5f);
    const float iy0 = fmaf(gy0 + 1.0f, half, -0.5f);

    const float dx = th0 - 1.0f;   // wx shift per +1 in w (same cell+1)
    const float dy = th4 - 1.0f;   // wy shift per +1 in h (same row step)

    // ---- warp-uniform fast path: 3 columns x 5 rows cover all 8 pixels ----
    {
        const float fxf = floorf(ix0), fyf = floorf(iy0);
        const int x0 = (int)fxf, y0 = (int)fyf;
        const float fx = ix0 - fxf, fy = iy0 - fyf;

        // corner weights (bilinear in p and j -> corners bound the tile)
        const float wx00 = fx;
        const float wx10 = fx + dx;
        const float wx03 = fmaf(3.0f, th1, fx);
        const float wx13 = wx03 + dx;
        const float wy00 = fy;
        const float wy10 = fy + th3;
        const float wy03 = fmaf(3.0f, dy, fy);
        const float wy13 = wy03 + th3;
        const float wxmn = fminf(fminf(wx00, wx10), fminf(wx03, wx13));
        const float wxmx = fmaxf(fmaxf(wx00, wx10), fmaxf(wx03, wx13));
        const float wymn = fminf(fminf(wy00, wy10), fminf(wy03, wy13));
        const float wymx = fmaxf(fmaxf(wy00, wy10), fmaxf(wy03, wy13));

        const bool ok = (wxmn >= 0.0f) & (wxmx < 1.0f)
                      & (wymn >= 0.0f) & (wymx < 1.0f)
                      & (x0 >= 0) & (x0 <= DIM - 3)
                      & (y0 >= 0) & (y0 <= DIM - 5);
        if (__all_sync(0xffffffffu, ok)) {
            float v0[5], v1[5], v2[5];
            const float* r = base + (size_t)y0 * DIM + x0;
#pragma unroll
            for (int k = 0; k < 5; k++) {
                v0[k] = __ldg(r);
                v1[k] = __ldg(r + 1);
                v2[k] = __ldg(r + 2);
                r += DIM;
            }
            float2 wk[4];
#pragma unroll
            for (int j = 0; j < 4; j++)
                wk[j] = __ldg((const float2*)(Wk + (h0 + j) * DIM + w));
#pragma unroll
            for (int j = 0; j < 4; j++) {
                const float wxa = fmaf((float)j, th1, fx);   // p=0
                const float wxb = wxa + dx;                  // p=1
                const float wya = fmaf((float)j, dy, fy);    // p=0
                const float wyb = wya + th3;                 // p=1
                const float top0 = fmaf(v1[j],     wxa, v0[j]     * (1.0f - wxa));
                const float bot0 = fmaf(v1[j + 1], wxa, v0[j + 1] * (1.0f - wxa));
                const float val0 = fmaf(bot0, wya, top0 * (1.0f - wya));
                const float top1 = fmaf(v2[j],     wxb, v1[j]     * (1.0f - wxb));
                const float bot1 = fmaf(v2[j + 1], wxb, v1[j + 1] * (1.0f - wxb));
                const float val1 = fmaf(bot1, wyb, top1 * (1.0f - wyb));
                st_cs2(xreg + obase + (size_t)j * DIM, val0, val1);
                c = fmaf(val0, wk[j].x, fmaf(val1, wk[j].y, c));
            }
            return;
        }
    }

    // ---- fallback: two verified single-column calls (exact semantics) ----
    sample_column_at<DIM>(base, Wk, xreg, obase, w, h0,
                          ix0, iy0, th1, th4, c);
    sample_column_at<DIM>(base, Wk, xreg, obase + 1, w + 1, h0,
                          ix0 + th0, iy0 + th3, th1, th4, c);
}

__device__ __forceinline__ void block_reduce_dot(float c, float* slot) {
#pragma unroll
    for (int o = 16; o; o >>= 1)
        c += __shfl_down_sync(0xffffffffu, c, o);
    __shared__ float sm[8];
    const int lane = threadIdx.x & 31;
    const int wrp  = threadIdx.x >> 5;
    if (lane == 0) sm[wrp] = c;
    __syncthreads();
    if (wrp == 0) {
        float v = (lane < 8) ? sm[lane] : 0.0f;
#pragma unroll
        for (int o = 4; o; o >>= 1)
            v += __shfl_down_sync(0xffffffffu, v, o);
        if (lane == 0) atomicAdd(slot, v);
    }
}

// ---------------- fused: avgpool pyramid + affine sample + dot (level 0) --------
// Block = 64-wide x 32-high tile; 256 threads, 2x4 pixels each.
__global__ __launch_bounds__(256) void fused512_kernel(
    const float* __restrict__ x,
    const float* __restrict__ theta,
    const float* __restrict__ Wk,
    float* __restrict__ xreg)
{
    const int t  = blockIdx.y;
    const int tx = blockIdx.x & 7;    // 8 tiles across (64 px)
    const int ty = blockIdx.x >> 3;   // 16 tiles down (32 px)
    const int tid = threadIdx.x;

    const float* base = x + (size_t)t * HW1;

    // ---------- Phase A: pooling (float4 loads; verified R15) ----------
    __shared__ float p2s[16][32];
    __shared__ float p4s[8][16];
    {
        const int px = tid & 15;
        const int py = tid >> 4;
        const int gx = tx * 64 + px * 4;
        const int gy = ty * 32 + py * 2;
        const float4 a = *(const float4*)(base + (size_t)gy * D1 + gx);
        const float4 b = *(const float4*)(base + (size_t)(gy + 1) * D1 + gx);
        const float v2a = (a.x + a.y + b.x + b.y) * 0.25f;
        const float v2b = (a.z + a.w + b.z + b.w) * 0.25f;
        p2s[py][2 * px]     = v2a;
        p2s[py][2 * px + 1] = v2b;
        *(float2*)(g_img2 + (size_t)t * HW2 + (size_t)(ty * 16 + py) * 256
                   + tx * 32 + 2 * px) = make_float2(v2a, v2b);
    }
    __syncthreads();
    if (tid < 128) {
        const int ix = tid & 15;
        const int iy = tid >> 4;
        const float v4 = (p2s[2*iy][2*ix] + p2s[2*iy][2*ix+1]
                        + p2s[2*iy+1][2*ix] + p2s[2*iy+1][2*ix+1]) * 0.25f;
        p4s[iy][ix] = v4;
        g_img4[(size_t)t * HW4 + (size_t)(ty * 8 + iy) * 128 + tx * 16 + ix] = v4;
    }
    __syncthreads();
    if (tid < 32) {
        const int ix = tid & 7;
        const int iy = tid >> 3;
        const float v8 = (p4s[2*iy][2*ix] + p4s[2*iy][2*ix+1]
                        + p4s[2*iy+1][2*ix] + p4s[2*iy+1][2*ix+1]) * 0.25f;
        g_img8[(size_t)t * HW8 + (size_t)(ty * 4 + iy) * 64 + tx * 8 + ix] = v8;
    }

    // ---------- Phase B: affine sample + dot (2x4 pixels/thread) ----------
    const int w  = tx * 64 + (tid & 31) * 2;
    const int h0 = ty * 32 + (tid >> 5) * 4;

    float c = 0.0f;
    const size_t obase = (size_t)t * HW1 + (size_t)h0 * D1 + w;
    sample_pair4<512>(base, theta + t * 6, Wk, xreg, obase, w, h0, c);
    block_reduce_dot(c, &g_s[t]);
}

// ---------------- affine sample + dot for the pooled levels (2x4 px/thread) ------
template<int DIM>
__global__ __launch_bounds__(256) void sample_dot_kernel(
    const float* __restrict__ img,
    const float* __restrict__ theta,
    const float* __restrict__ Wk,
    float* __restrict__ xreg,
    int level)
{
    constexpr int LOG = (DIM == 512) ? 9 : (DIM == 256) ? 8 : (DIM == 128) ? 7 : 6;
    const int t   = blockIdx.y;
    const int tid = blockIdx.x * blockDim.x + threadIdx.x;   // 0..HW/8-1
    const int w   = (tid & (DIM / 2 - 1)) * 2;
    const int h0  = (tid >> (LOG - 1)) << 2;

    const float* base = img + (size_t)t * (DIM * DIM);

    float c = 0.0f;
    const size_t obase = (size_t)t * (DIM * DIM) + (size_t)h0 * DIM + w;
    sample_pair4<DIM>(base, theta + t * 6, Wk, xreg, obase, w, h0, c);
    block_reduce_dot(c, &g_s[level * TT + t]);
}

// ---------------- rank-1 outer product: L[t,:] = s[t] * Wk ----------------
__global__ void outer_kernel(const float* __restrict__ Wk,
                             float* __restrict__ L,
                             int level, int hw4) {
    int t = blockIdx.y;
    int i = blockIdx.x * blockDim.x + threadIdx.x;
    float sv = g_s[level * TT + t];
    float4 wv = __ldg((const float4*)Wk + i);
    float4 o = make_float4(sv * wv.x, sv * wv.y, sv * wv.z, sv * wv.w);
    st_cs4((float*)((float4*)L + (size_t)t * hw4 + i), o);
}

extern "C" void kernel_launch(void* const* d_in, const int* in_sizes, int n_in,
                              void* d_out, int out_size) {
    const float* x     = (const float*)d_in[0];
    const float* theta = (const float*)d_in[1];
    const float* W1    = (const float*)d_in[2];
    const float* W2    = (const float*)d_in[3];
    const float* W4    = (const float*)d_in[4];
    const float* W8    = (const float*)d_in[5];
    float* out = (float*)d_out;

    size_t off = 0;
    float* xr1 = out + off; off += (size_t)TT * HW1;
    float* L1  = out + off; off += (size_t)TT * HW1;
    float* xr2 = out + off; off += (size_t)TT * HW2;
    float* L2  = out + off; off += (size_t)TT * HW2;
    float* xr4 = out + off; off += (size_t)TT * HW4;
    float* L4  = out + off; off += (size_t)TT * HW4;
    float* xr8 = out + off; off += (size_t)TT * HW8;
    float* L8  = out + off; off += (size_t)TT * HW8;

    void *p2, *p4, *p8;
    cudaGetSymbolAddress(&p2, g_img2);
    cudaGetSymbolAddress(&p4, g_img4);
    cudaGetSymbolAddress(&p8, g_img8);
    const float* i2 = (const float*)p2;
    const float* i4 = (const float*)p4;
    const float* i8 = (const float*)p8;

    static cudaStream_t s1 = nullptr, s2 = nullptr;
    static cudaEvent_t ef = nullptr, e1 = nullptr, e2 = nullptr;
    if (s1 == nullptr) {
        cudaStreamCreateWithFlags(&s1, cudaStreamNonBlocking);
        cudaStreamCreateWithFlags(&s2, cudaStreamNonBlocking);
        cudaEventCreateWithFlags(&ef, cudaEventDisableTiming);
        cudaEventCreateWithFlags(&e1, cudaEventDisableTiming);
        cudaEventCreateWithFlags(&e2, cudaEventDisableTiming);
    }
    cudaStream_t s0 = 0;

    // serial head: zero accumulators, fused level-0 (pool + sample + dot)
    zero_s_kernel<<<1, 4 * TT, 0, s0>>>();
    fused512_kernel<<<dim3(128, TT), 256, 0, s0>>>(x, theta, W1, xr1);
    cudaEventRecord(ef, s0);

    // fork: outer1 (pure writes) on s1
    cudaStreamWaitEvent(s1, ef, 0);
    outer_kernel<<<dim3(HW1 / 1024, TT), 256, 0, s1>>>(W1, L1, 0, HW1 / 4);
    cudaEventRecord(e1, s1);

    // small levels on s2
    cudaStreamWaitEvent(s2, ef, 0);
    sample_dot_kernel<128><<<dim3(HW4 / 2048, TT), 256, 0, s2>>>(i4, theta, W4, xr4, 2);
    outer_kernel<<<dim3(HW4 / 1024, TT), 256, 0, s2>>>(W4, L4, 2, HW4 / 4);
    sample_dot_kernel< 64><<<dim3(HW8 / 2048, TT), 256, 0, s2>>>(i8, theta, W8, xr8, 3);
    outer_kernel<<<dim3(HW8 / 1024, TT), 256, 0, s2>>>(W8, L8, 3, HW8 / 4);
    cudaEventRecord(e2, s2);

    // level-1 chain on s0 (critical tail path)
    sample_dot_kernel<256><<<dim3(HW2 / 2048, TT), 256, 0, s0>>>(i2, theta, W2, xr2, 1);
    outer_kernel<<<dim3(HW2 / 1024, TT), 256, 0, s0>>>(W2, L2, 1, HW2 / 4);

    // join
    cudaStreamWaitEvent(s0, e1, 0);
    cudaStreamWaitEvent(s0, e2, 0);
}

// round 17
// speedup vs baseline: 1.0942x; 1.0942x over previous
#include <cuda_runtime.h>

// ---------------- problem constants ----------------
#define TT 256
#define D1 512
#define HW1 (512*512)
#define HW2 (256*256)
#define HW4 (128*128)
#define HW8 (64*64)

// ---------------- device scratch (no allocations allowed) ----------------
__device__ float g_img2[(size_t)TT * HW2];
__device__ float g_img4[(size_t)TT * HW4];
__device__ float g_img8[(size_t)TT * HW8];
__device__ float g_s[4 * TT];

__device__ __forceinline__ void st_cs(float* p, float v) {
    asm volatile("st.global.cs.f32 [%0], %1;" :: "l"(p), "f"(v) : "memory");
}
__device__ __forceinline__ void st_cs4(float* p, float4 v) {
    asm volatile("st.global.cs.v4.f32 [%0], {%1,%2,%3,%4};"
                 :: "l"(p), "f"(v.x), "f"(v.y), "f"(v.z), "f"(v.w) : "memory");
}

__global__ void zero_s_kernel() {
    g_s[threadIdx.x] = 0.0f;
}

// ============ verified R15 core: 4-high single column, precomputed coords ============
template<int DIM>
__device__ __forceinline__ void sample_column_at(
    const float* __restrict__ base, const float* __restrict__ Wk,
    float* __restrict__ xreg, size_t obase,
    int w, int h0,
    float ix0, float iy0, float th1, float th4,
    float& c)
{
    // ---- warp-uniform fast path ----
    {
        const float fx0f = floorf(ix0), fy0f = floorf(iy0);
        const int x0 = (int)fx0f, y0 = (int)fy0f;
        const float fx = ix0 - fx0f, fy = iy0 - fy0f;
        const float dy = th4 - 1.0f;
        const float wxe = fmaf(3.0f, th1, fx);
        const float wye = fmaf(3.0f, dy,  fy);
        const bool ok = (wxe >= 0.0f) & (wxe < 1.0f)
                      & (wye >= 0.0f) & (wye < 1.0f)
                      & (x0 >= 0) & (x0 < DIM - 1)
                      & (y0 >= 0) & (y0 <= DIM - 5);
        if (__all_sync(0xffffffffu, ok)) {
            float va[5], vb[5];
            const float* r = base + (size_t)y0 * DIM + x0;
#pragma unroll
            for (int k = 0; k < 5; k++) {
                va[k] = __ldg(r);
                vb[k] = __ldg(r + 1);
                r += DIM;
            }
            float wk[4];
#pragma unroll
            for (int j = 0; j < 4; j++)
                wk[j] = __ldg(Wk + (h0 + j) * DIM + w);
#pragma unroll
            for (int j = 0; j < 4; j++) {
                const float wx = fmaf((float)j, th1, fx);
                const float wy = fmaf((float)j, dy,  fy);
                const float top = fmaf(vb[j],     wx, va[j]     * (1.0f - wx));
                const float bot = fmaf(vb[j + 1], wx, va[j + 1] * (1.0f - wx));
                const float val = fmaf(bot, wy, top * (1.0f - wy));
                st_cs(xreg + obase + (size_t)j * DIM, val);
                c = fmaf(val, wk[j], c);
            }
            return;
        }
    }

    // ---- general path (verified): per-j gathers, interior/border split ----
    const float ix3 = fmaf(3.0f, th1, ix0);
    const float iy3 = fmaf(3.0f, th4, iy0);
    const bool interior =
        fminf(ix0, ix3) >= 0.0f && fmaxf(ix0, ix3) < (float)(DIM - 1) &&
        fminf(iy0, iy3) >= 0.0f && fmaxf(iy0, iy3) < (float)(DIM - 1);

    if (interior) {
        float v00[4], v01[4], v10[4], v11[4], wxs[4], wys[4], wk[4];
#pragma unroll
        for (int j = 0; j < 4; j++) {
            const float ix = fmaf((float)j, th1, ix0);
            const float iy = fmaf((float)j, th4, iy0);
            const float fx = floorf(ix), fy = floorf(iy);
            const int x0 = (int)fx, y0 = (int)fy;
            wxs[j] = ix - fx; wys[j] = iy - fy;
            const float* r0 = base + (size_t)y0 * DIM + x0;
            const float* r1 = r0 + DIM;
            v00[j] = __ldg(r0);
            v01[j] = __ldg(r0 + 1);
            v10[j] = __ldg(r1);
            v11[j] = __ldg(r1 + 1);
            wk[j]  = __ldg(Wk + (h0 + j) * DIM + w);
        }
#pragma unroll
        for (int j = 0; j < 4; j++) {
            const float wx = wxs[j], wy = wys[j];
            const float top = fmaf(v01[j], wx, v00[j] * (1.0f - wx));
            const float bot = fmaf(v11[j], wx, v10[j] * (1.0f - wx));
            const float val = fmaf(bot, wy, top * (1.0f - wy));
            st_cs(xreg + obase + (size_t)j * DIM, val);
            c = fmaf(val, wk[j], c);
        }
    } else {
#pragma unroll
        for (int j = 0; j < 4; j++) {
            const float ix = fmaf((float)j, th1, ix0);
            const float iy = fmaf((float)j, th4, iy0);
            const float fx = floorf(ix), fy = floorf(iy);
            const int x0 = (int)fx, y0 = (int)fy;
            const float wx = ix - fx, wy = iy - fy;

            const bool x0v = (unsigned)x0       < (unsigned)DIM;
            const bool x1v = (unsigned)(x0 + 1) < (unsigned)DIM;
            const bool y0v = (unsigned)y0       < (unsigned)DIM;
            const bool y1v = (unsigned)(y0 + 1) < (unsigned)DIM;

            const int x0c = min(max(x0, 0), DIM - 1);
            const int x1c = min(max(x0 + 1, 0), DIM - 1);
            const int y0c = min(max(y0, 0), DIM - 1);
            const int y1c = min(max(y0 + 1, 0), DIM - 1);

            const float* r0 = base + (size_t)y0c * DIM;
            const float* r1 = base + (size_t)y1c * DIM;
            const float a00 = __ldg(r0 + x0c);
            const float a01 = __ldg(r0 + x1c);
            const float a10 = __ldg(r1 + x0c);
            const float a11 = __ldg(r1 + x1c);

            const float wx1 = x1v ? wx : 0.0f;
            const float wx0 = x0v ? (1.0f - wx) : 0.0f;
            const float wy1 = y1v ? wy : 0.0f;
            const float wy0 = y0v ? (1.0f - wy) : 0.0f;

            const float top = fmaf(a01, wx1, a00 * wx0);
            const float bot = fmaf(a11, wx1, a10 * wx0);
            const float val = fmaf(bot, wy1, top * wy0);
            st_cs(xreg + obase + (size_t)j * DIM, val);
            c = fmaf(val, __ldg(Wk + (h0 + j) * DIM + w), c);
        }
    }
}

// ============ 8-high column: one uniformity check, rolling 2-batch gathers ============
template<int DIM>
__device__ __forceinline__ void sample_column8(
    const float* __restrict__ base, const float* __restrict__ theta_t,
    const float* __restrict__ Wk, float* __restrict__ xreg,
    size_t obase8, int w, int h0, float& c)
{
    const float th0 = __ldg(theta_t + 0), th1 = __ldg(theta_t + 1), th2 = __ldg(theta_t + 2);
    const float th3 = __ldg(theta_t + 3), th4 = __ldg(theta_t + 4), th5 = __ldg(theta_t + 5);

    constexpr float inv  = 2.0f / (float)DIM;
    constexpr float half = 0.5f * (float)DIM;
    const float xn  = ((float)w  + 0.5f) * inv - 1.0f;
    const float yn0 = ((float)h0 + 0.5f) * inv - 1.0f;
    const float gx0 = fmaf(th0, xn, fmaf(th1, yn0, th2));
    const float gy0 = fmaf(th3, xn, fmaf(th4, yn0, th5));
    const float ix0 = fmaf(gx0 + 1.0f, half, -0.5f);
    const float iy0 = fmaf(gy0 + 1.0f, half, -0.5f);

    // ---- single 8-row warp-uniform check (endpoints bound all j) ----
    {
        const float fxf = floorf(ix0), fyf = floorf(iy0);
        const int x0 = (int)fxf, y0 = (int)fyf;
        const float fx = ix0 - fxf, fy = iy0 - fyf;
        const float dy = th4 - 1.0f;
        const float wxe = fmaf(7.0f, th1, fx);
        const float wye = fmaf(7.0f, dy,  fy);
        const bool ok = (wxe >= 0.0f) & (wxe < 1.0f)
                      & (wye >= 0.0f) & (wye < 1.0f)
                      & (x0 >= 0) & (x0 < DIM - 1)
                      & (y0 >= 0) & (y0 <= DIM - 9);
        if (__all_sync(0xffffffffu, ok)) {
            float va[5], vb[5];
            const float* r = base + (size_t)y0 * DIM + x0;
#pragma unroll
            for (int k = 0; k < 5; k++) {
                va[k] = __ldg(r);
                vb[k] = __ldg(r + 1);
                r += DIM;
            }
            // batch A: j = 0..3
#pragma unroll
            for (int j = 0; j < 4; j++) {
                const float wx = fmaf((float)j, th1, fx);
                const float wy = fmaf((float)j, dy,  fy);
                const float wkj = __ldg(Wk + (h0 + j) * DIM + w);
                const float top = fmaf(vb[j],     wx, va[j]     * (1.0f - wx));
                const float bot = fmaf(vb[j + 1], wx, va[j + 1] * (1.0f - wx));
                const float val = fmaf(bot, wy, top * (1.0f - wy));
                st_cs(xreg + obase8 + (size_t)j * DIM, val);
                c = fmaf(val, wkj, c);
            }
            // roll: row 4 becomes row 0 of batch B; load rows 5..8
            va[0] = va[4]; vb[0] = vb[4];
#pragma unroll
            for (int k = 1; k < 5; k++) {
                va[k] = __ldg(r);
                vb[k] = __ldg(r + 1);
                r += DIM;
            }
            // batch B: j = 4..7 (row index j-4 within batch)
#pragma unroll
            for (int j = 4; j < 8; j++) {
                const float wx = fmaf((float)j, th1, fx);
                const float wy = fmaf((float)j, dy,  fy);
                const float wkj = __ldg(Wk + (h0 + j) * DIM + w);
                const float top = fmaf(vb[j - 4],     wx, va[j - 4]     * (1.0f - wx));
                const float bot = fmaf(vb[j - 3],     wx, va[j - 3]     * (1.0f - wx));
                const float val = fmaf(bot, wy, top * (1.0f - wy));
                st_cs(xreg + obase8 + (size_t)j * DIM, val);
                c = fmaf(val, wkj, c);
            }
            return;
        }
    }

    // ---- fallback: two verified 4-row columns (R15 semantics) ----
    sample_column_at<DIM>(base, Wk, xreg, obase8, w, h0,
                          ix0, iy0, th1, th4, c);
    sample_column_at<DIM>(base, Wk, xreg, obase8 + (size_t)4 * DIM, w, h0 + 4,
                          fmaf(4.0f, th1, ix0), fmaf(4.0f, th4, iy0), th1, th4, c);
}

__device__ __forceinline__ void block_reduce_dot(float c, float* slot) {
#pragma unroll
    for (int o = 16; o; o >>= 1)
        c += __shfl_down_sync(0xffffffffu, c, o);
    __shared__ float sm[8];
    const int lane = threadIdx.x & 31;
    const int wrp  = threadIdx.x >> 5;
    if (lane == 0) sm[wrp] = c;
    __syncthreads();
    if (wrp == 0) {
        float v = (lane < 8) ? sm[lane] : 0.0f;
#pragma unroll
        for (int o = 4; o; o >>= 1)
            v += __shfl_down_sync(0xffffffffu, v, o);
        if (lane == 0) atomicAdd(slot, v);
    }
}

// ---------------- fused: avgpool pyramid + affine sample + dot (level 0) --------
// Block = 64-wide x 32-high tile; 256 threads, 8 output pixels each.
__global__ __launch_bounds__(256) void fused512_kernel(
    const float* __restrict__ x,
    const float* __restrict__ theta,
    const float* __restrict__ Wk,
    float* __restrict__ xreg)
{
    const int t  = blockIdx.y;
    const int tx = blockIdx.x & 7;    // 8 tiles across (64 px)
    const int ty = blockIdx.x >> 3;   // 16 tiles down (32 px)
    const int tid = threadIdx.x;

    const float* base = x + (size_t)t * HW1;

    // ---------- Phase A: pooling (float4 loads; verified R15) ----------
    __shared__ float p2s[16][32];
    __shared__ float p4s[8][16];
    {
        const int px = tid & 15;
        const int py = tid >> 4;
        const int gx = tx * 64 + px * 4;
        const int gy = ty * 32 + py * 2;
        const float4 a = *(const float4*)(base + (size_t)gy * D1 + gx);
        const float4 b = *(const float4*)(base + (size_t)(gy + 1) * D1 + gx);
        const float v2a = (a.x + a.y + b.x + b.y) * 0.25f;
        const float v2b = (a.z + a.w + b.z + b.w) * 0.25f;
        p2s[py][2 * px]     = v2a;
        p2s[py][2 * px + 1] = v2b;
        *(float2*)(g_img2 + (size_t)t * HW2 + (size_t)(ty * 16 + py) * 256
                   + tx * 32 + 2 * px) = make_float2(v2a, v2b);
    }
    __syncthreads();
    if (tid < 128) {
        const int ix = tid & 15;
        const int iy = tid >> 4;
        const float v4 = (p2s[2*iy][2*ix] + p2s[2*iy][2*ix+1]
                        + p2s[2*iy+1][2*ix] + p2s[2*iy+1][2*ix+1]) * 0.25f;
        p4s[iy][ix] = v4;
        g_img4[(size_t)t * HW4 + (size_t)(ty * 8 + iy) * 128 + tx * 16 + ix] = v4;
    }
    __syncthreads();
    if (tid < 32) {
        const int ix = tid & 7;
        const int iy = tid >> 3;
        const float v8 = (p4s[2*iy][2*ix] + p4s[2*iy][2*ix+1]
                        + p4s[2*iy+1][2*ix] + p4s[2*iy+1][2*ix+1]) * 0.25f;
        g_img8[(size_t)t * HW8 + (size_t)(ty * 4 + iy) * 64 + tx * 8 + ix] = v8;
    }

    // ---------- Phase B: affine sample + dot (8 pixels/thread, lanes stride-1 in w) ----
    const int w  = tx * 64 + (tid & 63);
    const int h0 = ty * 32 + (tid >> 6) * 8;

    float c = 0.0f;
    const size_t obase8 = (size_t)t * HW1 + (size_t)h0 * D1 + w;
    sample_column8<512>(base, theta + t * 6, Wk, xreg, obase8, w, h0, c);
    block_reduce_dot(c, &g_s[t]);
}

// ---------------- affine sample + dot for the pooled levels (8 px/thread) --------
template<int DIM>
__global__ __launch_bounds__(256) void sample_dot_kernel(
    const float* __restrict__ img,
    const float* __restrict__ theta,
    const float* __restrict__ Wk,
    float* __restrict__ xreg,
    int level)
{
    constexpr int LOG = (DIM == 512) ? 9 : (DIM == 256) ? 8 : (DIM == 128) ? 7 : 6;
    const int t   = blockIdx.y;
    const int tid = blockIdx.x * blockDim.x + threadIdx.x;   // 0..HW/8-1
    const int w   = tid & (DIM - 1);
    const int h0  = (tid >> LOG) << 3;

    const float* base = img + (size_t)t * (DIM * DIM);

    float c = 0.0f;
    const size_t obase8 = (size_t)t * (DIM * DIM) + (size_t)h0 * DIM + w;
    sample_column8<DIM>(base, theta + t * 6, Wk, xreg, obase8, w, h0, c);
    block_reduce_dot(c, &g_s[level * TT + t]);
}

// ---------------- rank-1 outer product: L[t,:] = s[t] * Wk ----------------
__global__ void outer_kernel(const float* __restrict__ Wk,
                             float* __restrict__ L,
                             int level, int hw4) {
    int t = blockIdx.y;
    int i = blockIdx.x * blockDim.x + threadIdx.x;
    float sv = g_s[level * TT + t];
    float4 wv = __ldg((const float4*)Wk + i);
    float4 o = make_float4(sv * wv.x, sv * wv.y, sv * wv.z, sv * wv.w);
    st_cs4((float*)((float4*)L + (size_t)t * hw4 + i), o);
}

extern "C" void kernel_launch(void* const* d_in, const int* in_sizes, int n_in,
                              void* d_out, int out_size) {
    const float* x     = (const float*)d_in[0];
    const float* theta = (const float*)d_in[1];
    const float* W1    = (const float*)d_in[2];
    const float* W2    = (const float*)d_in[3];
    const float* W4    = (const float*)d_in[4];
    const float* W8    = (const float*)d_in[5];
    float* out = (float*)d_out;

    size_t off = 0;
    float* xr1 = out + off; off += (size_t)TT * HW1;
    float* L1  = out + off; off += (size_t)TT * HW1;
    float* xr2 = out + off; off += (size_t)TT * HW2;
    float* L2  = out + off; off += (size_t)TT * HW2;
    float* xr4 = out + off; off += (size_t)TT * HW4;
    float* L4  = out + off; off += (size_t)TT * HW4;
    float* xr8 = out + off; off += (size_t)TT * HW8;
    float* L8  = out + off; off += (size_t)TT * HW8;

    void *p2, *p4, *p8;
    cudaGetSymbolAddress(&p2, g_img2);
    cudaGetSymbolAddress(&p4, g_img4);
    cudaGetSymbolAddress(&p8, g_img8);
    const float* i2 = (const float*)p2;
    const float* i4 = (const float*)p4;
    const float* i8 = (const float*)p8;

    static cudaStream_t s1 = nullptr, s2 = nullptr;
    static cudaEvent_t ef = nullptr, e1 = nullptr, e2 = nullptr;
    if (s1 == nullptr) {
        cudaStreamCreateWithFlags(&s1, cudaStreamNonBlocking);
        cudaStreamCreateWithFlags(&s2, cudaStreamNonBlocking);
        cudaEventCreateWithFlags(&ef, cudaEventDisableTiming);
        cudaEventCreateWithFlags(&e1, cudaEventDisableTiming);
        cudaEventCreateWithFlags(&e2, cudaEventDisableTiming);
    }
    cudaStream_t s0 = 0;

    // serial head: zero accumulators, fused level-0 (pool + sample + dot)
    zero_s_kernel<<<1, 4 * TT, 0, s0>>>();
    fused512_kernel<<<dim3(128, TT), 256, 0, s0>>>(x, theta, W1, xr1);
    cudaEventRecord(ef, s0);

    // fork: outer1 (pure writes) on s1
    cudaStreamWaitEvent(s1, ef, 0);
    outer_kernel<<<dim3(HW1 / 1024, TT), 256, 0, s1>>>(W1, L1, 0, HW1 / 4);
    cudaEventRecord(e1, s1);

    // small levels on s2
    cudaStreamWaitEvent(s2, ef, 0);
    sample_dot_kernel<128><<<dim3(HW4 / 2048, TT), 256, 0, s2>>>(i4, theta, W4, xr4, 2);
    outer_kernel<<<dim3(HW4 / 1024, TT), 256, 0, s2>>>(W4, L4, 2, HW4 / 4);
    sample_dot_kernel< 64><<<dim3(HW8 / 2048, TT), 256, 0, s2>>>(i8, theta, W8, xr8, 3);
    outer_kernel<<<dim3(HW8 / 1024, TT), 256, 0, s2>>>(W8, L8, 3, HW8 / 4);
    cudaEventRecord(e2, s2);

    // level-1 chain on s0 (critical tail path)
    sample_dot_kernel<256><<<dim3(HW2 / 2048, TT), 256, 0, s0>>>(i2, theta, W2, xr2, 1);
    outer_kernel<<<dim3(HW2 / 1024, TT), 256, 0, s0>>>(W2, L2, 1, HW2 / 4);

    // join
    cudaStreamWaitEvent(s0, e1, 0);
    cudaStreamWaitEvent(s0, e2, 0);
}